// round 2
// baseline (speedup 1.0000x reference)
#include <cuda_runtime.h>

#define BB 4
#define LL 8192
#define DD 512
#define NC 64      // chunks along L
#define CL 128     // chunk length = LL/NC

// Scratch: per (b, chunk, d) complex carry state. 4*64*512*8 B = 1 MB.
__device__ float2 g_carry[BB * NC * DD];

// ---------------------------------------------------------------------------
// Pass 1: local scan per chunk from zero state; store end state.
// grid = (DD/256, BB, NC), block = 256
// ---------------------------------------------------------------------------
__global__ void lru_pass1(const float* __restrict__ x,
                          const float* __restrict__ nu,
                          const float* __restrict__ theta) {
    const int d = blockIdx.x * blockDim.x + threadIdx.x;
    const int b = blockIdx.y;
    const int c = blockIdx.z;

    const float a   = expf(nu[d]);
    const float mag = expf(-a);
    float s, co;
    sincosf(theta[d], &s, &co);
    const float lr = mag * co;
    const float li = mag * s;

    const float* xp = x + ((size_t)(b * LL + c * CL)) * DD + d;

    float hr = 0.f, hi = 0.f;
#pragma unroll 8
    for (int i = 0; i < CL; i++) {
        const float xv = xp[(size_t)i * DD];
        const float nhr = fmaf(lr, hr, fmaf(-li, hi, xv));
        const float nhi = fmaf(li, hr, lr * hi);
        hr = nhr;
        hi = nhi;
    }
    g_carry[(b * NC + c) * DD + d] = make_float2(hr, hi);
}

// ---------------------------------------------------------------------------
// Pass 2: scan across chunks per (b,d) with multiplier lambda^CL.
// Replaces local end-states with true *incoming* states per chunk.
// ---------------------------------------------------------------------------
__global__ void lru_pass2(const float* __restrict__ nu,
                          const float* __restrict__ theta) {
    const int idx = blockIdx.x * blockDim.x + threadIdx.x;  // b*DD + d
    if (idx >= BB * DD) return;
    const int b = idx / DD;
    const int d = idx % DD;

    const float a    = expf(nu[d]);
    const float Lmag = expf(-(float)CL * a);
    float s, co;
    sincosf((float)CL * theta[d], &s, &co);
    const float Lr = Lmag * co;
    const float Li = Lmag * s;

    float2* cp = g_carry + (size_t)b * NC * DD + d;
    float cr = 0.f, ci = 0.f;
#pragma unroll
    for (int c = 0; c < NC; c++) {
        const float2 loc = cp[(size_t)c * DD];
        cp[(size_t)c * DD] = make_float2(cr, ci);   // incoming state for chunk c
        const float ncr = fmaf(Lr, cr, fmaf(-Li, ci, loc.x));
        const float nci = fmaf(Li, cr, fmaf(Lr, ci, loc.y));
        cr = ncr;
        ci = nci;
    }
}

// ---------------------------------------------------------------------------
// Pass 3: rerun local scan seeded with true incoming state; emit outputs.
// grid = (DD/256, BB, NC), block = 256
// ---------------------------------------------------------------------------
__global__ void lru_pass3(const float* __restrict__ x,
                          const float* __restrict__ nu,
                          const float* __restrict__ theta,
                          const float* __restrict__ gre,
                          const float* __restrict__ gim,
                          float* __restrict__ out) {
    const int d = blockIdx.x * blockDim.x + threadIdx.x;
    const int b = blockIdx.y;
    const int c = blockIdx.z;

    const float a   = expf(nu[d]);
    const float mag = expf(-a);
    float s, co;
    sincosf(theta[d], &s, &co);
    const float lr = mag * co;
    const float li = mag * s;
    const float gr = gre[d];
    const float gi = gim[d];

    const float2 h0 = g_carry[(b * NC + c) * DD + d];
    float hr = h0.x, hi = h0.y;

    const size_t base = ((size_t)(b * LL + c * CL)) * DD + d;
    const float* xp = x + base;
    float* yp = out + base;

#pragma unroll 8
    for (int i = 0; i < CL; i++) {
        const float xv = xp[(size_t)i * DD];
        const float nhr = fmaf(lr, hr, fmaf(-li, hi, xv));
        const float nhi = fmaf(li, hr, lr * hi);
        hr = nhr;
        hi = nhi;
        yp[(size_t)i * DD] = fmaf(gr, hr, -gi * hi);
    }
}

// ---------------------------------------------------------------------------
extern "C" void kernel_launch(void* const* d_in, const int* in_sizes, int n_in,
                              void* d_out, int out_size) {
    const float* x     = (const float*)d_in[0];
    const float* nu    = (const float*)d_in[1];
    const float* theta = (const float*)d_in[2];
    const float* gre   = (const float*)d_in[3];
    const float* gim   = (const float*)d_in[4];
    float* out = (float*)d_out;

    dim3 grid1(DD / 256, BB, NC);
    lru_pass1<<<grid1, 256>>>(x, nu, theta);
    lru_pass2<<<(BB * DD + 255) / 256, 256>>>(nu, theta);
    lru_pass3<<<grid1, 256>>>(x, nu, theta, gre, gim, out);
}

// round 3
// speedup vs baseline: 1.1447x; 1.1447x over previous
#include <cuda_runtime.h>

#define BB 4
#define LL 8192
#define DD 512
#define NC 128     // chunks along L
#define CL 64      // chunk length = LL/NC

// Scratch: per (b, chunk, d) complex carry state. 4*128*512*8 B = 2 MB.
__device__ float2 g_carry[BB * NC * DD];

// ---------------------------------------------------------------------------
// Pass 1: local scan per chunk from zero state; store end state.
// grid = (DD/256, BB, NC), block = 256
// ---------------------------------------------------------------------------
__global__ void lru_pass1(const float* __restrict__ x,
                          const float* __restrict__ nu,
                          const float* __restrict__ theta) {
    const int d = blockIdx.x * blockDim.x + threadIdx.x;
    const int b = blockIdx.y;
    const int c = blockIdx.z;

    const float a   = expf(nu[d]);
    const float mag = expf(-a);
    float s, co;
    sincosf(theta[d], &s, &co);
    const float lr = mag * co;
    const float li = mag * s;

    const float* xp = x + ((size_t)(b * LL + c * CL)) * DD + d;

    float hr = 0.f, hi = 0.f;
#pragma unroll 16
    for (int i = 0; i < CL; i++) {
        const float xv = xp[(size_t)i * DD];
        const float nhr = fmaf(lr, hr, fmaf(-li, hi, xv));
        const float nhi = fmaf(li, hr, lr * hi);
        hr = nhr;
        hi = nhi;
    }
    g_carry[(b * NC + c) * DD + d] = make_float2(hr, hi);
}

// ---------------------------------------------------------------------------
// Pass 2: scan across chunks per (b,d) with multiplier lambda^CL.
// Replaces local end-states with true *incoming* states per chunk.
// ---------------------------------------------------------------------------
__global__ void lru_pass2(const float* __restrict__ nu,
                          const float* __restrict__ theta) {
    const int idx = blockIdx.x * blockDim.x + threadIdx.x;  // b*DD + d
    if (idx >= BB * DD) return;
    const int b = idx / DD;
    const int d = idx % DD;

    const float a    = expf(nu[d]);
    const float Lmag = expf(-(float)CL * a);
    float s, co;
    sincosf((float)CL * theta[d], &s, &co);
    const float Lr = Lmag * co;
    const float Li = Lmag * s;

    float2* cp = g_carry + (size_t)b * NC * DD + d;
    float cr = 0.f, ci = 0.f;
#pragma unroll
    for (int c = 0; c < NC; c++) {
        const float2 loc = cp[(size_t)c * DD];
        cp[(size_t)c * DD] = make_float2(cr, ci);   // incoming state for chunk c
        const float ncr = fmaf(Lr, cr, fmaf(-Li, ci, loc.x));
        const float nci = fmaf(Li, cr, fmaf(Lr, ci, loc.y));
        cr = ncr;
        ci = nci;
    }
}

// ---------------------------------------------------------------------------
// Pass 3: rerun local scan seeded with true incoming state; emit outputs.
// Output stores use streaming hint so y-writes don't evict x from L2
// (pass1 just warmed L2 with all of x).
// grid = (DD/256, BB, NC), block = 256
// ---------------------------------------------------------------------------
__global__ void lru_pass3(const float* __restrict__ x,
                          const float* __restrict__ nu,
                          const float* __restrict__ theta,
                          const float* __restrict__ gre,
                          const float* __restrict__ gim,
                          float* __restrict__ out) {
    const int d = blockIdx.x * blockDim.x + threadIdx.x;
    const int b = blockIdx.y;
    const int c = blockIdx.z;

    const float a   = expf(nu[d]);
    const float mag = expf(-a);
    float s, co;
    sincosf(theta[d], &s, &co);
    const float lr = mag * co;
    const float li = mag * s;
    const float gr = gre[d];
    const float gi = gim[d];

    const float2 h0 = g_carry[(b * NC + c) * DD + d];
    float hr = h0.x, hi = h0.y;

    const size_t base = ((size_t)(b * LL + c * CL)) * DD + d;
    const float* xp = x + base;
    float* yp = out + base;

#pragma unroll 16
    for (int i = 0; i < CL; i++) {
        const float xv = xp[(size_t)i * DD];
        const float nhr = fmaf(lr, hr, fmaf(-li, hi, xv));
        const float nhi = fmaf(li, hr, lr * hi);
        hr = nhr;
        hi = nhi;
        __stcs(yp + (size_t)i * DD, fmaf(gr, hr, -gi * hi));
    }
}

// ---------------------------------------------------------------------------
extern "C" void kernel_launch(void* const* d_in, const int* in_sizes, int n_in,
                              void* d_out, int out_size) {
    const float* x     = (const float*)d_in[0];
    const float* nu    = (const float*)d_in[1];
    const float* theta = (const float*)d_in[2];
    const float* gre   = (const float*)d_in[3];
    const float* gim   = (const float*)d_in[4];
    float* out = (float*)d_out;

    dim3 grid1(DD / 256, BB, NC);
    lru_pass1<<<grid1, 256>>>(x, nu, theta);
    lru_pass2<<<(BB * DD + 255) / 256, 256>>>(nu, theta);
    lru_pass3<<<grid1, 256>>>(x, nu, theta, gre, gim, out);
}